// round 13
// baseline (speedup 1.0000x reference)
#include <cuda_runtime.h>

// CTC loss forward. One CTA (4 warps) per batch element.
//   warp 0: forward alpha DP, t = 0..127   (linear domain, per-lane rescale)
//   warp 1: backward beta DP, t = 255..128
//   warp 2: sum of log2 Z_t for rows 0..127    (pure streaming reduction)
//   warp 3: sum of log2 Z_t for rows 128..255
// Combine: loglik_raw = sum_s alpha_m(s)*beta_m(s) at m=127; subtract Z sum.
// DP warps load ONLY 2 scalars per step (blank logit: lane-uniform; label
// logit: gather), prefetched 8 deep — no full-row loads, no butterfly, no
// per-step normalization. Z warps stream full rows via float4 and keep DRAM
// saturated; DP gathers then hit L2. All math in log2/linear-raw domain.

#define TN 256
#define HT 128
#define CN 128
#define LN 32
#define PADV 127
#define LOG2E 1.4426950408889634f
#define NLN2 0.6931471805599453f

__device__ __forceinline__ float ex2(float x) {
    float r; asm("ex2.approx.f32 %0, %1;" : "=f"(r) : "f"(x)); return r;
}
__device__ __forceinline__ float lg2(float x) {
    float r; asm("lg2.approx.f32 %0, %1;" : "=f"(r) : "f"(x)); return r;
}

__global__ __launch_bounds__(128) void ctc_ws_kernel(
    const int* __restrict__ yt, const float* __restrict__ yp,
    float* __restrict__ out)
{
    const unsigned FULL = 0xffffffffu;
    __shared__ float s_bo[LN], s_be[LN], s_off[LN];
    __shared__ float s_b0;
    __shared__ double s_z[2];

    const int tid = threadIdx.x;
    const int wid = tid >> 5;
    const int l = tid & 31;
    const int b = blockIdx.x;
    const float* __restrict__ rowf = yp + (size_t)b * TN * CN;
    const float4* __restrict__ row4 = (const float4*)rowf;

    const int lab = yt[b * LN + l];
    const unsigned msk = __ballot_sync(FULL, lab != PADV);
    const int len = __popc(msk);

    if (wid >= 2) {
        // ------------- Z warps: sum log2(sum_c exp2(x_c)) over 128 rows ----
        const int base = (wid == 2) ? 0 : HT;
        float4 rg[4];
        #pragma unroll
        for (int i = 0; i < 4; ++i) rg[i] = row4[(base + i) * 32 + l];
        double zsum = 0.0;
        #pragma unroll 4
        for (int k = 0; k < HT; ++k) {
            const float4 v = rg[k & 3];
            const int rn = base + ((k + 4 < HT) ? (k + 4) : (HT - 1));
            rg[k & 3] = row4[rn * 32 + l];
            float s = ex2(v.x * LOG2E) + ex2(v.y * LOG2E)
                    + ex2(v.z * LOG2E) + ex2(v.w * LOG2E);
            #pragma unroll
            for (int o = 16; o; o >>= 1) s += __shfl_xor_sync(FULL, s, o);
            zsum += (double)lg2(s);
        }
        if (l == 0) s_z[wid - 2] = zsum;
        __syncthreads();
    } else if (wid == 1) {
        // ------------- backward beta, rows r = 255..128 --------------------
        const int labn = __shfl_down_sync(FULL, lab, 1);
        const float skipD = (l < 31 && lab != labn) ? 1.0f : 0.0f;

        float xl[8], xb[8];
        #pragma unroll
        for (int i = 0; i < 8; ++i) {
            const int r = TN - 1 - i;
            xl[i] = __ldg(rowf + r * CN + lab);
            xb[i] = __ldg(rowf + r * CN);
        }

        float b_odd = (l == len - 1) ? 1.0f : 0.0f;
        float b_even = b_odd;
        float b0 = 0.0f, off = 0.0f, cD = 1.0f;

        #pragma unroll 4
        for (int k0 = 0; k0 < HT; ++k0) {
            const float pl = ex2(xl[k0 & 7] * LOG2E);
            const float pb = ex2(xb[k0 & 7] * LOG2E);
            if (k0 + 8 < HT) {
                const int r = TN - 1 - (k0 + 8);
                xl[k0 & 7] = __ldg(rowf + r * CN + lab);
                xb[k0 & 7] = __ldg(rowf + r * CN);
            }

            const float g_odd = pl * b_odd;
            const float g_even = pb * b_even;
            float gd = __shfl_down_sync(FULL, g_odd, 1) * cD;
            gd = (l < 31) ? gd : 0.0f;
            b0 = pb * b0 + g_odd;               // valid on lane 0
            const float n_odd  = g_odd + g_even + skipD * gd;
            const float n_even = g_even + gd;
            b_odd = n_odd; b_even = n_even;

            if ((k0 & 3) == 3) {
                const float m = fmaxf(b_odd, fmaxf(b_even, (l == 0) ? b0 : 0.0f));
                int eb = (__float_as_int(m) >> 23) & 255;
                int k = (eb == 0) ? 0 : (eb - 127);
                k = (k > 120) ? 120 : k;
                const float sc = __int_as_float((127 - k) << 23);
                b_odd *= sc; b_even *= sc; b0 *= sc;
                off += (float)k;
                cD = ex2(__shfl_down_sync(FULL, off, 1) - off);
            }
        }

        s_bo[l] = b_odd;
        s_be[l] = b_even;
        s_off[l] = off;
        if (l == 0) s_b0 = b0;
        __syncthreads();
    } else {
        // ------------- forward alpha, t = 0..127 ---------------------------
        const int labp = __shfl_up_sync(FULL, lab, 1);
        const float skipf = (l >= 1 && lab != labp) ? 1.0f : 0.0f;

        float xl[8], xb[8];
        #pragma unroll
        for (int i = 0; i < 8; ++i) {
            xl[i] = __ldg(rowf + i * CN + lab);
            xb[i] = __ldg(rowf + i * CN);
        }

        float a_odd = 0.0f, a_even = 0.0f, off = 0.0f, c = 1.0f;
        float a0lin = 1.0f;

        #pragma unroll 4
        for (int t = 0; t < HT; ++t) {
            const float pl = ex2(xl[t & 7] * LOG2E);
            const float pb = ex2(xb[t & 7] * LOG2E);
            if (t + 8 < HT) {
                xl[t & 7] = __ldg(rowf + (t + 8) * CN + lab);
                xb[t & 7] = __ldg(rowf + (t + 8) * CN);
            }

            const float e0 = a0lin;
            a0lin *= pb;

            float po = __shfl_up_sync(FULL, a_odd, 1);
            float pe = __shfl_up_sync(FULL, a_even, 1);
            pe = (l == 0) ? e0 : pe * c;
            const float pos = po * c * skipf;
            const float n_odd  = pl * (a_odd + pe + pos);
            const float n_even = pb * (a_even + a_odd);
            a_odd = n_odd; a_even = n_even;

            if ((t & 3) == 3) {
                const float m = fmaxf(a_odd, a_even);
                int eb = (__float_as_int(m) >> 23) & 255;
                int k = (eb == 0) ? 0 : (eb - 127);
                k = (k > 120) ? 120 : k;
                const float sc = __int_as_float((127 - k) << 23);
                a_odd *= sc; a_even *= sc; a0lin *= sc;
                off += (float)k;
                c = ex2(__shfl_up_sync(FULL, off, 1) - off);
            }
        }

        __syncthreads();   // beta + Z results visible

        // combine: loglik_raw = sum_s alpha(s)*beta(s)
        float val = a_odd * s_bo[l] + a_even * s_be[l];
        float e = off + s_off[l];
        if (l == 0) val += a0lin * s_b0;
        float ll = lg2(fmaxf(val, 1e-45f)) + e;
        float mm = ll;
        #pragma unroll
        for (int o = 16; o; o >>= 1) mm = fmaxf(mm, __shfl_xor_sync(FULL, mm, o));
        float se = ex2(ll - mm);
        #pragma unroll
        for (int o = 16; o; o >>= 1) se += __shfl_xor_sync(FULL, se, o);
        if (l == 0) {
            const float llraw = mm + lg2(se);
            const float cumZ = (float)(s_z[0] + s_z[1]);
            out[b] = (cumZ - llraw) * NLN2;
        }
    }
}

extern "C" void kernel_launch(void* const* d_in, const int* in_sizes, int n_in,
                              void* d_out, int out_size) {
    const int* y_true = (const int*)d_in[0];     // [1024, 32] int32
    const float* y_pred = (const float*)d_in[1]; // [1024, 256, 128] float32
    float* out = (float*)d_out;                  // [1024] float32
    const int B = in_sizes[0] / LN;              // 1024
    ctc_ws_kernel<<<B, 128>>>(y_true, y_pred, out);
}

// round 14
// speedup vs baseline: 2.2311x; 2.2311x over previous
#include <cuda_runtime.h>

// CTC loss forward. One CTA (4 warps) per batch element.
//   warp 0: forward alpha DP, t = 0..127   (linear domain, per-lane rescale)
//   warp 1: backward beta DP, t = 255..128
//   warp 2: sum of log2 Z_t rows 0..127    (float4 streaming + butterfly)
//   warp 3: sum of log2 Z_t rows 128..255
// Combine at m=127: loglik_raw = sum_s alpha(s)*beta(s); subtract Z sum.
// DP warps load ONLY 2 scalars/step (blank: lane-uniform LDG; label: gather),
// ring prefetched 8 deep with FULL unroll-8 (compile-time ring indices, regs
// only) and pointer-increment addressing (LDG [ptr+imm], no per-step ALU).

#define TN 256
#define HT 128
#define CN 128
#define LN 32
#define PADV 127
#define LOG2E 1.4426950408889634f
#define NLN2 0.6931471805599453f

__device__ __forceinline__ float ex2(float x) {
    float r; asm("ex2.approx.f32 %0, %1;" : "=f"(r) : "f"(x)); return r;
}
__device__ __forceinline__ float lg2(float x) {
    float r; asm("lg2.approx.f32 %0, %1;" : "=f"(r) : "f"(x)); return r;
}

__global__ __launch_bounds__(128) void ctc_ws2_kernel(
    const int* __restrict__ yt, const float* __restrict__ yp,
    float* __restrict__ out)
{
    const unsigned FULL = 0xffffffffu;
    __shared__ float s_bo[LN], s_be[LN], s_off[LN];
    __shared__ float s_b0;
    __shared__ double s_z[2];

    const int tid = threadIdx.x;
    const int wid = tid >> 5;
    const int l = tid & 31;
    const int b = blockIdx.x;
    const float* __restrict__ rowf = yp + (size_t)b * TN * CN;
    const float4* __restrict__ row4 = (const float4*)rowf;

    const int lab = yt[b * LN + l];
    const unsigned msk = __ballot_sync(FULL, lab != PADV);
    const int len = __popc(msk);

    if (wid >= 2) {
        // ---- Z warps: sum log2(sum_c exp2(x_c)) over their 128 rows -------
        const int base = (wid == 2) ? 0 : HT;
        float4 rg[4];
        #pragma unroll
        for (int i = 0; i < 4; ++i) rg[i] = row4[(base + i) * 32 + l];
        double zsum = 0.0;
        #pragma unroll 4
        for (int k = 0; k < HT; ++k) {
            const float4 v = rg[k & 3];
            const int rn = base + ((k + 4 < HT) ? (k + 4) : (HT - 1));
            rg[k & 3] = row4[rn * 32 + l];
            float s = ex2(v.x * LOG2E) + ex2(v.y * LOG2E)
                    + ex2(v.z * LOG2E) + ex2(v.w * LOG2E);
            #pragma unroll
            for (int o = 16; o; o >>= 1) s += __shfl_xor_sync(FULL, s, o);
            zsum += (double)lg2(s);
        }
        if (l == 0) s_z[wid - 2] = zsum;
        __syncthreads();
    } else if (wid == 1) {
        // ---- backward beta, rows r = 255..128 -----------------------------
        const int labn = __shfl_down_sync(FULL, lab, 1);
        const float skipD = (l < 31 && lab != labn) ? 1.0f : 0.0f;

        const float* pb_ptr = rowf + (TN - 1) * CN;        // row 255, class 0
        const float* pl_ptr = pb_ptr + lab;                // row 255, class lab
        float xb[8], xl[8];
        #pragma unroll
        for (int i = 0; i < 8; ++i) {
            xb[i] = __ldg(pb_ptr - i * CN);
            xl[i] = __ldg(pl_ptr - i * CN);
        }
        pb_ptr -= 8 * CN; pl_ptr -= 8 * CN;

        float b_odd = (l == len - 1) ? 1.0f : 0.0f;
        float b_even = b_odd;
        float b0 = 0.0f, off = 0.0f, cD = 1.0f;

        for (int g = 0; g < HT / 8; ++g) {
            const bool pf = (g + 1 < HT / 8);
            #pragma unroll
            for (int i = 0; i < 8; ++i) {
                const float pl = ex2(xl[i] * LOG2E);
                const float pb = ex2(xb[i] * LOG2E);
                if (pf) {
                    xb[i] = __ldg(pb_ptr - i * CN);
                    xl[i] = __ldg(pl_ptr - i * CN);
                }

                const float g_odd = pl * b_odd;
                const float g_even = pb * b_even;
                float gd = __shfl_down_sync(FULL, g_odd, 1) * cD;
                gd = (l < 31) ? gd : 0.0f;
                b0 = pb * b0 + g_odd;                       // valid on lane 0
                const float n_odd  = g_odd + g_even + skipD * gd;
                const float n_even = g_even + gd;
                b_odd = n_odd; b_even = n_even;

                if ((i & 3) == 3) {
                    const float m = fmaxf(b_odd,
                        fmaxf(b_even, (l == 0) ? b0 : 0.0f));
                    int eb = (__float_as_int(m) >> 23) & 255;
                    int k = (eb == 0) ? 0 : (eb - 127);
                    k = (k > 120) ? 120 : k;
                    const float sc = __int_as_float((127 - k) << 23);
                    b_odd *= sc; b_even *= sc; b0 *= sc;
                    off += (float)k;
                    cD = ex2(__shfl_down_sync(FULL, off, 1) - off);
                }
            }
            pb_ptr -= 8 * CN; pl_ptr -= 8 * CN;
        }

        s_bo[l] = b_odd;
        s_be[l] = b_even;
        s_off[l] = off;
        if (l == 0) s_b0 = b0;
        __syncthreads();
    } else {
        // ---- forward alpha, t = 0..127 ------------------------------------
        const int labp = __shfl_up_sync(FULL, lab, 1);
        const float skipf = (l >= 1 && lab != labp) ? 1.0f : 0.0f;

        const float* pb_ptr = rowf;                        // row 0, class 0
        const float* pl_ptr = rowf + lab;
        float xb[8], xl[8];
        #pragma unroll
        for (int i = 0; i < 8; ++i) {
            xb[i] = __ldg(pb_ptr + i * CN);
            xl[i] = __ldg(pl_ptr + i * CN);
        }
        pb_ptr += 8 * CN; pl_ptr += 8 * CN;

        float a_odd = 0.0f, a_even = 0.0f, off = 0.0f, c = 1.0f;
        float a0lin = 1.0f;

        for (int g = 0; g < HT / 8; ++g) {
            const bool pf = (g + 1 < HT / 8);
            #pragma unroll
            for (int i = 0; i < 8; ++i) {
                const float pl = ex2(xl[i] * LOG2E);
                const float pb = ex2(xb[i] * LOG2E);
                if (pf) {
                    xb[i] = __ldg(pb_ptr + i * CN);
                    xl[i] = __ldg(pl_ptr + i * CN);
                }

                const float e0 = a0lin;
                a0lin *= pb;

                float po = __shfl_up_sync(FULL, a_odd, 1);
                float pe = __shfl_up_sync(FULL, a_even, 1);
                pe = (l == 0) ? e0 : pe * c;
                const float pos = po * c * skipf;
                const float n_odd  = pl * (a_odd + pe + pos);
                const float n_even = pb * (a_even + a_odd);
                a_odd = n_odd; a_even = n_even;

                if ((i & 3) == 3) {
                    const float m = fmaxf(a_odd, a_even);
                    int eb = (__float_as_int(m) >> 23) & 255;
                    int k = (eb == 0) ? 0 : (eb - 127);
                    k = (k > 120) ? 120 : k;
                    const float sc = __int_as_float((127 - k) << 23);
                    a_odd *= sc; a_even *= sc; a0lin *= sc;
                    off += (float)k;
                    c = ex2(__shfl_up_sync(FULL, off, 1) - off);
                }
            }
            pb_ptr += 8 * CN; pl_ptr += 8 * CN;
        }

        __syncthreads();   // beta + Z results visible

        // combine: loglik_raw = sum_s alpha(s)*beta(s)
        float val = a_odd * s_bo[l] + a_even * s_be[l];
        float e = off + s_off[l];
        if (l == 0) val += a0lin * s_b0;
        float ll = lg2(fmaxf(val, 1e-45f)) + e;
        float mm = ll;
        #pragma unroll
        for (int o = 16; o; o >>= 1) mm = fmaxf(mm, __shfl_xor_sync(FULL, mm, o));
        float se = ex2(ll - mm);
        #pragma unroll
        for (int o = 16; o; o >>= 1) se += __shfl_xor_sync(FULL, se, o);
        if (l == 0) {
            const float llraw = mm + lg2(se);
            const float cumZ = (float)(s_z[0] + s_z[1]);
            out[b] = (cumZ - llraw) * NLN2;
        }
    }
}

extern "C" void kernel_launch(void* const* d_in, const int* in_sizes, int n_in,
                              void* d_out, int out_size) {
    const int* y_true = (const int*)d_in[0];     // [1024, 32] int32
    const float* y_pred = (const float*)d_in[1]; // [1024, 256, 128] float32
    float* out = (float*)d_out;                  // [1024] float32
    const int B = in_sizes[0] / LN;              // 1024
    ctc_ws2_kernel<<<B, 128>>>(y_true, y_pred, out);
}

// round 15
// speedup vs baseline: 2.3816x; 1.0674x over previous
#include <cuda_runtime.h>

// CTC loss forward. One CTA (6 warps, 192 thr) per batch element.
//   warp 0: forward alpha DP, t = 0..127   (linear domain, per-lane rescale)
//   warp 1: backward beta DP, t = 255..128
//   warps 2-5: sum of log2 Z_t, 64 rows each (4 rows/iter: 8-lane groups own
//              a row, 16 classes/lane; 3 SHFL + 1 LG2 per 4 rows; ring depth 2)
// Combine at m=127: loglik_raw = sum_s alpha(s)*beta(s); subtract Z sum.
// DP warps load 2 scalars/step (blank: uniform LDG; label: gather), ring 8
// deep, full unroll-8 (reg-resident rings, pointer-increment addressing).

#define TN 256
#define HT 128
#define CN 128
#define LN 32
#define PADV 127
#define LOG2E 1.4426950408889634f
#define NLN2 0.6931471805599453f

__device__ __forceinline__ float ex2(float x) {
    float r; asm("ex2.approx.f32 %0, %1;" : "=f"(r) : "f"(x)); return r;
}
__device__ __forceinline__ float lg2(float x) {
    float r; asm("lg2.approx.f32 %0, %1;" : "=f"(r) : "f"(x)); return r;
}

__global__ __launch_bounds__(192) void ctc_ws3_kernel(
    const int* __restrict__ yt, const float* __restrict__ yp,
    float* __restrict__ out)
{
    const unsigned FULL = 0xffffffffu;
    __shared__ float s_bo[LN], s_be[LN], s_off[LN];
    __shared__ float s_b0;
    __shared__ double s_z[4];

    const int tid = threadIdx.x;
    const int wid = tid >> 5;
    const int l = tid & 31;
    const int b = blockIdx.x;
    const float* __restrict__ rowf = yp + (size_t)b * TN * CN;
    const float4* __restrict__ row4 = (const float4*)rowf;

    if (wid >= 2) {
        // ---- Z warps: 64 rows each, 4 rows per iteration ------------------
        // 8-lane group g owns row base+it*4+g; lane seg = l&7 covers classes
        // [seg*16, seg*16+16) via 4 float4 loads.
        const int base = (wid - 2) * 64;
        const int grp = l >> 3;        // 0..3: row within the 4-row pack
        const int seg = l & 7;         // 16-class segment
        const float4* p0 = row4 + (size_t)(base + grp) * 32 + seg * 4;

        float4 v[2][4];
        #pragma unroll
        for (int j = 0; j < 4; ++j) v[0][j] = p0[j];
        #pragma unroll
        for (int j = 0; j < 4; ++j) v[1][j] = p0[4 * 32 + j];

        double zacc = 0.0;
        for (int it = 0; it < 16; ++it) {
            const int cu = it & 1;
            float s = 0.0f;
            #pragma unroll
            for (int j = 0; j < 4; ++j) {
                const float4 q = v[cu][j];
                s += ex2(q.x * LOG2E) + ex2(q.y * LOG2E)
                   + ex2(q.z * LOG2E) + ex2(q.w * LOG2E);
            }
            if (it + 2 < 16) {
                const float4* pn = p0 + (size_t)(it + 2) * 4 * 32;
                #pragma unroll
                for (int j = 0; j < 4; ++j) v[cu][j] = pn[j];
            }
            // reduce within each 8-lane group (3 shuffles for all 4 rows)
            s += __shfl_xor_sync(FULL, s, 1);
            s += __shfl_xor_sync(FULL, s, 2);
            s += __shfl_xor_sync(FULL, s, 4);
            zacc += (double)lg2(s);
        }
        // zacc uniform within each 8-lane group; reduce across the 4 groups
        zacc += __shfl_xor_sync(FULL, zacc, 8);
        zacc += __shfl_xor_sync(FULL, zacc, 16);
        if (l == 0) s_z[wid - 2] = zacc;
        __syncthreads();
    } else if (wid == 1) {
        // ---- backward beta, rows r = 255..128 -----------------------------
        const int lab = yt[b * LN + l];
        const unsigned msk = __ballot_sync(FULL, lab != PADV);
        const int len = __popc(msk);
        const int labn = __shfl_down_sync(FULL, lab, 1);
        const float skipD = (l < 31 && lab != labn) ? 1.0f : 0.0f;

        const float* pb_ptr = rowf + (TN - 1) * CN;        // row 255, class 0
        const float* pl_ptr = pb_ptr + lab;
        float xb[8], xl[8];
        #pragma unroll
        for (int i = 0; i < 8; ++i) {
            xb[i] = __ldg(pb_ptr - i * CN);
            xl[i] = __ldg(pl_ptr - i * CN);
        }
        pb_ptr -= 8 * CN; pl_ptr -= 8 * CN;

        float b_odd = (l == len - 1) ? 1.0f : 0.0f;
        float b_even = b_odd;
        float b0 = 0.0f, off = 0.0f, cD = 1.0f;

        for (int g = 0; g < HT / 8; ++g) {
            const bool pf = (g + 1 < HT / 8);
            #pragma unroll
            for (int i = 0; i < 8; ++i) {
                const float pl = ex2(xl[i] * LOG2E);
                const float pb = ex2(xb[i] * LOG2E);
                if (pf) {
                    xb[i] = __ldg(pb_ptr - i * CN);
                    xl[i] = __ldg(pl_ptr - i * CN);
                }

                const float g_odd = pl * b_odd;
                const float g_even = pb * b_even;
                float gd = __shfl_down_sync(FULL, g_odd, 1) * cD;
                gd = (l < 31) ? gd : 0.0f;
                b0 = pb * b0 + g_odd;                       // valid on lane 0
                const float n_odd  = g_odd + g_even + skipD * gd;
                const float n_even = g_even + gd;
                b_odd = n_odd; b_even = n_even;

                if ((i & 3) == 3) {
                    const float m = fmaxf(b_odd,
                        fmaxf(b_even, (l == 0) ? b0 : 0.0f));
                    int eb = (__float_as_int(m) >> 23) & 255;
                    int k = (eb == 0) ? 0 : (eb - 127);
                    k = (k > 120) ? 120 : k;
                    const float sc = __int_as_float((127 - k) << 23);
                    b_odd *= sc; b_even *= sc; b0 *= sc;
                    off += (float)k;
                    cD = ex2(__shfl_down_sync(FULL, off, 1) - off);
                }
            }
            pb_ptr -= 8 * CN; pl_ptr -= 8 * CN;
        }

        s_bo[l] = b_odd;
        s_be[l] = b_even;
        s_off[l] = off;
        if (l == 0) s_b0 = b0;
        __syncthreads();
    } else {
        // ---- forward alpha, t = 0..127 ------------------------------------
        const int lab = yt[b * LN + l];
        const int labp = __shfl_up_sync(FULL, lab, 1);
        const float skipf = (l >= 1 && lab != labp) ? 1.0f : 0.0f;

        const float* pb_ptr = rowf;                        // row 0, class 0
        const float* pl_ptr = rowf + lab;
        float xb[8], xl[8];
        #pragma unroll
        for (int i = 0; i < 8; ++i) {
            xb[i] = __ldg(pb_ptr + i * CN);
            xl[i] = __ldg(pl_ptr + i * CN);
        }
        pb_ptr += 8 * CN; pl_ptr += 8 * CN;

        float a_odd = 0.0f, a_even = 0.0f, off = 0.0f, c = 1.0f;
        float a0lin = 1.0f;

        for (int g = 0; g < HT / 8; ++g) {
            const bool pf = (g + 1 < HT / 8);
            #pragma unroll
            for (int i = 0; i < 8; ++i) {
                const float pl = ex2(xl[i] * LOG2E);
                const float pb = ex2(xb[i] * LOG2E);
                if (pf) {
                    xb[i] = __ldg(pb_ptr + i * CN);
                    xl[i] = __ldg(pl_ptr + i * CN);
                }

                const float e0 = a0lin;
                a0lin *= pb;

                float po = __shfl_up_sync(FULL, a_odd, 1);
                float pe = __shfl_up_sync(FULL, a_even, 1);
                pe = (l == 0) ? e0 : pe * c;
                const float pos = po * c * skipf;
                const float n_odd  = pl * (a_odd + pe + pos);
                const float n_even = pb * (a_even + a_odd);
                a_odd = n_odd; a_even = n_even;

                if ((i & 3) == 3) {
                    const float m = fmaxf(a_odd, a_even);
                    int eb = (__float_as_int(m) >> 23) & 255;
                    int k = (eb == 0) ? 0 : (eb - 127);
                    k = (k > 120) ? 120 : k;
                    const float sc = __int_as_float((127 - k) << 23);
                    a_odd *= sc; a_even *= sc; a0lin *= sc;
                    off += (float)k;
                    c = ex2(__shfl_up_sync(FULL, off, 1) - off);
                }
            }
            pb_ptr += 8 * CN; pl_ptr += 8 * CN;
        }

        __syncthreads();   // beta + Z results visible

        // combine: loglik_raw = sum_s alpha(s)*beta(s)
        float val = a_odd * s_bo[l] + a_even * s_be[l];
        float e = off + s_off[l];
        if (l == 0) val += a0lin * s_b0;
        float ll = lg2(fmaxf(val, 1e-45f)) + e;
        float mm = ll;
        #pragma unroll
        for (int o = 16; o; o >>= 1) mm = fmaxf(mm, __shfl_xor_sync(FULL, mm, o));
        float se = ex2(ll - mm);
        #pragma unroll
        for (int o = 16; o; o >>= 1) se += __shfl_xor_sync(FULL, se, o);
        if (l == 0) {
            const float llraw = mm + lg2(se);
            const float cumZ = (float)(s_z[0] + s_z[1] + s_z[2] + s_z[3]);
            out[b] = (cumZ - llraw) * NLN2;
        }
    }
}

extern "C" void kernel_launch(void* const* d_in, const int* in_sizes, int n_in,
                              void* d_out, int out_size) {
    const int* y_true = (const int*)d_in[0];     // [1024, 32] int32
    const float* y_pred = (const float*)d_in[1]; // [1024, 256, 128] float32
    float* out = (float*)d_out;                  // [1024] float32
    const int B = in_sizes[0] / LN;              // 1024
    ctc_ws3_kernel<<<B, 192>>>(y_true, y_pred, out);
}